// round 1
// baseline (speedup 1.0000x reference)
#include <cuda_runtime.h>

#define B_  2
#define T_  2048
#define C_  1024
#define H_  16
#define HD_ 64

__device__ float g_Q[(size_t)B_ * H_ * T_ * HD_];
__device__ float g_K[(size_t)B_ * H_ * T_ * HD_];
__device__ float g_V[(size_t)B_ * H_ * T_ * HD_];
__device__ float g_Y[(size_t)B_ * T_ * C_];

// Packed f32x2 helpers (sm_103a; ptxas never emits FFMA2 from plain C++)
#define FFMA2(acc, a, b) asm("fma.rn.f32x2 %0, %1, %2, %0;" : "+l"(acc) : "l"(a), "l"(b))
#define PACK2(out, lo, hi) asm("mov.b64 %0, {%1, %2};" : "=l"(out) : "f"(lo), "f"(hi))
#define UNPACK2(lo, hi, in) asm("mov.b64 {%0, %1}, %2;" : "=f"(lo), "=f"(hi) : "l"(in))

// ---------------------------------------------------------------------------
// SGEMM: C[M,N] = A[M,1024] @ W[1024,N] + bias, 128x128 tile, BK=16,
// 256 threads, 8x8 per thread, f32x2-packed inner product (M-paired).
// scatter=1: write to [b,h,t,d] layout (QKV). scatter=0: row-major.
// ---------------------------------------------------------------------------
__device__ __forceinline__ void gemm_tile_1024(
    const float* __restrict__ A, const float* __restrict__ W,
    const float* __restrict__ bias, float* __restrict__ Out, int scatter)
{
    __shared__ float As[16 * 132];  // [k][m] transposed, padded stride 132
    __shared__ float Bs[16 * 128];  // [k][n]

    const int tid = threadIdx.x;
    const int bm0 = blockIdx.y * 128;
    const int bn0 = blockIdx.x * 128;
    const int tm = tid >> 4;
    const int tn = tid & 15;

    unsigned long long acc2[4][8];
#pragma unroll
    for (int p = 0; p < 4; p++)
#pragma unroll
        for (int j = 0; j < 8; j++) acc2[p][j] = 0ull;

    const int fi0 = tid, fi1 = tid + 256;
    const int ar0 = fi0 >> 2, ak0 = (fi0 & 3) * 4;
    const int ar1 = fi1 >> 2, ak1 = (fi1 & 3) * 4;
    const int br0 = fi0 >> 5, bc0 = (fi0 & 31) * 4;
    const int br1 = fi1 >> 5, bc1 = (fi1 & 31) * 4;

    for (int k0 = 0; k0 < 1024; k0 += 16) {
        float4 a0 = *(const float4*)(A + (size_t)(bm0 + ar0) * 1024 + k0 + ak0);
        float4 a1 = *(const float4*)(A + (size_t)(bm0 + ar1) * 1024 + k0 + ak1);
        float4 b0 = *(const float4*)(W + (size_t)(k0 + br0) * 1024 + bn0 + bc0);
        float4 b1 = *(const float4*)(W + (size_t)(k0 + br1) * 1024 + bn0 + bc1);
        As[(ak0 + 0) * 132 + ar0] = a0.x; As[(ak0 + 1) * 132 + ar0] = a0.y;
        As[(ak0 + 2) * 132 + ar0] = a0.z; As[(ak0 + 3) * 132 + ar0] = a0.w;
        As[(ak1 + 0) * 132 + ar1] = a1.x; As[(ak1 + 1) * 132 + ar1] = a1.y;
        As[(ak1 + 2) * 132 + ar1] = a1.z; As[(ak1 + 3) * 132 + ar1] = a1.w;
        *(float4*)(Bs + br0 * 128 + bc0) = b0;
        *(float4*)(Bs + br1 * 128 + bc1) = b1;
        __syncthreads();

#pragma unroll
        for (int kk = 0; kk < 16; kk++) {
            const float* arow = As + kk * 132 + tm * 8;
            const float* brow = Bs + kk * 128 + tn * 8;
            unsigned long long av[4];
#pragma unroll
            for (int p = 0; p < 4; p++)
                av[p] = *(const unsigned long long*)(arow + 2 * p);
            float bsc[8];
            *(float4*)(bsc)     = *(const float4*)(brow);
            *(float4*)(bsc + 4) = *(const float4*)(brow + 4);
            unsigned long long bd[8];
#pragma unroll
            for (int j = 0; j < 8; j++) PACK2(bd[j], bsc[j], bsc[j]);
#pragma unroll
            for (int p = 0; p < 4; p++)
#pragma unroll
                for (int j = 0; j < 8; j++) FFMA2(acc2[p][j], av[p], bd[j]);
        }
        __syncthreads();
    }

#pragma unroll
    for (int p = 0; p < 4; p++) {
        const int r0 = bm0 + tm * 8 + 2 * p;
#pragma unroll
        for (int j = 0; j < 8; j++) {
            float v0, v1;
            UNPACK2(v0, v1, acc2[p][j]);
            const int c = bn0 + tn * 8 + j;
            const float bb = bias[c];
            v0 += bb; v1 += bb;
            if (scatter) {
                const int h = c >> 6, d = c & 63;
                const int b0i = r0 >> 11, t0 = r0 & 2047;
                const int r1 = r0 + 1;
                const int b1i = r1 >> 11, t1 = r1 & 2047;
                Out[((((size_t)b0i * H_ + h) * T_ + t0) << 6) + d] = v0;
                Out[((((size_t)b1i * H_ + h) * T_ + t1) << 6) + d] = v1;
            } else {
                Out[(size_t)r0 * C_ + c] = v0;
                Out[(size_t)(r0 + 1) * C_ + c] = v1;
            }
        }
    }
}

__global__ void __launch_bounds__(256) qkv_gemm(
    const float* __restrict__ X,
    const float* __restrict__ Wq, const float* __restrict__ bq,
    const float* __restrict__ Wk, const float* __restrict__ bk,
    const float* __restrict__ Wv, const float* __restrict__ bv)
{
    const float* W; const float* bb; float* O;
    if (blockIdx.z == 0)      { W = Wq; bb = bq; O = g_Q; }
    else if (blockIdx.z == 1) { W = Wk; bb = bk; O = g_K; }
    else                      { W = Wv; bb = bv; O = g_V; }
    gemm_tile_1024(X, W, bb, O, 1);
}

__global__ void __launch_bounds__(256) proj_gemm(
    const float* __restrict__ Wp, const float* __restrict__ bp,
    float* __restrict__ Out)
{
    gemm_tile_1024(g_Y, Wp, bp, Out, 0);
}

// ---------------------------------------------------------------------------
// Flash attention, fp32. One CTA = 64 q-rows of one (b,h). 256 threads.
// Thread (ty,tx) owns S[16i+ty][16j+tx] and O[16i+ty][16jd+tx], i,j,jd in 0..3.
// Shared strides chosen for conflict-free hot reads: Qs/Ks 66, Ps 67, Vs 68.
// P tile aliases the K tile buffer.
// ---------------------------------------------------------------------------
__global__ void __launch_bounds__(256) flash_kernel()
{
    extern __shared__ float sm[];
    float* Qs  = sm;                         // 64*66
    float* KPs = sm + 64 * 66;               // max(64*66, 64*67) = 4288 floats
    float* Vs  = sm + 64 * 66 + 64 * 67;     // 64*68

    const int qt = (int)gridDim.x - 1 - (int)blockIdx.x;  // heavy tiles first
    const int h = blockIdx.y, b = blockIdx.z;
    const size_t base = ((size_t)(b * H_ + h)) * T_ * HD_;
    const float* Qg = g_Q + base;
    const float* Kg = g_K + base;
    const float* Vg = g_V + base;

    const int tid = threadIdx.x;
    const int ty = tid >> 4, tx = tid & 15;
    const int q0 = qt * 64;

    // Load Q tile once
#pragma unroll
    for (int lp = 0; lp < 4; lp++) {
        int fi = tid + lp * 256;
        int row = fi >> 4, cc = (fi & 15) * 4;
        float4 v = *(const float4*)(Qg + (size_t)(q0 + row) * HD_ + cc);
        float* dst = Qs + row * 66 + cc;
        dst[0] = v.x; dst[1] = v.y; dst[2] = v.z; dst[3] = v.w;
    }

    float mrow[4], lrow[4], o[4][4];
#pragma unroll
    for (int i = 0; i < 4; i++) {
        mrow[i] = -1e30f; lrow[i] = 0.f;
#pragma unroll
        for (int jd = 0; jd < 4; jd++) o[i][jd] = 0.f;
    }

    for (int kt = 0; kt <= qt; kt++) {
        __syncthreads();  // prior-iter P/V reads done; Q visible on first iter
#pragma unroll
        for (int lp = 0; lp < 4; lp++) {
            int fi = tid + lp * 256;
            int row = fi >> 4, cc = (fi & 15) * 4;
            float4 kv = *(const float4*)(Kg + (size_t)(kt * 64 + row) * HD_ + cc);
            float* kd = KPs + row * 66 + cc;
            kd[0] = kv.x; kd[1] = kv.y; kd[2] = kv.z; kd[3] = kv.w;
            *(float4*)(Vs + row * 68 + cc) =
                *(const float4*)(Vg + (size_t)(kt * 64 + row) * HD_ + cc);
        }
        __syncthreads();

        // S = Q @ K^T
        float s[4][4];
#pragma unroll
        for (int i = 0; i < 4; i++)
#pragma unroll
            for (int j = 0; j < 4; j++) s[i][j] = 0.f;

#pragma unroll 16
        for (int d = 0; d < 64; d++) {
            float qr[4], kr[4];
#pragma unroll
            for (int i = 0; i < 4; i++) qr[i] = Qs[(i * 16 + ty) * 66 + d];
#pragma unroll
            for (int j = 0; j < 4; j++) kr[j] = KPs[(j * 16 + tx) * 66 + d];
#pragma unroll
            for (int i = 0; i < 4; i++)
#pragma unroll
                for (int j = 0; j < 4; j++) s[i][j] = fmaf(qr[i], kr[j], s[i][j]);
        }

        // scale + causal mask (only diagonal tile needs masking)
        const bool diag = (kt == qt);
#pragma unroll
        for (int i = 0; i < 4; i++)
#pragma unroll
            for (int j = 0; j < 4; j++) {
                float v = s[i][j] * 0.125f;
                if (diag && (j * 16 + tx) > (i * 16 + ty)) v = -1e30f;
                s[i][j] = v;
            }

        // online softmax (row stats replicated across the 16 tx lanes)
#pragma unroll
        for (int i = 0; i < 4; i++) {
            float mx = fmaxf(fmaxf(s[i][0], s[i][1]), fmaxf(s[i][2], s[i][3]));
#pragma unroll
            for (int off = 1; off < 16; off <<= 1)
                mx = fmaxf(mx, __shfl_xor_sync(0xffffffffu, mx, off));
            const float mn = fmaxf(mrow[i], mx);
            const float alpha = __expf(mrow[i] - mn);
            mrow[i] = mn;
            float rs = 0.f;
#pragma unroll
            for (int j = 0; j < 4; j++) {
                float p = __expf(s[i][j] - mn);
                s[i][j] = p; rs += p;
            }
#pragma unroll
            for (int off = 1; off < 16; off <<= 1)
                rs += __shfl_xor_sync(0xffffffffu, rs, off);
            lrow[i] = lrow[i] * alpha + rs;
#pragma unroll
            for (int jd = 0; jd < 4; jd++) o[i][jd] *= alpha;
        }

        __syncthreads();  // all K reads done -> safe to alias P over K
#pragma unroll
        for (int i = 0; i < 4; i++)
#pragma unroll
            for (int j = 0; j < 4; j++)
                KPs[(i * 16 + ty) * 67 + j * 16 + tx] = s[i][j];
        __syncthreads();

        // O += P @ V
#pragma unroll 8
        for (int k = 0; k < 64; k++) {
            float pr[4], vr[4];
#pragma unroll
            for (int i = 0; i < 4; i++) pr[i] = KPs[(i * 16 + ty) * 67 + k];
#pragma unroll
            for (int jd = 0; jd < 4; jd++) vr[jd] = Vs[k * 68 + jd * 16 + tx];
#pragma unroll
            for (int i = 0; i < 4; i++)
#pragma unroll
                for (int jd = 0; jd < 4; jd++)
                    o[i][jd] = fmaf(pr[i], vr[jd], o[i][jd]);
        }
    }

    // normalize + write to [b,t,c]
#pragma unroll
    for (int i = 0; i < 4; i++) {
        const float inv = 1.0f / lrow[i];
        const int q = q0 + i * 16 + ty;
#pragma unroll
        for (int jd = 0; jd < 4; jd++) {
            const int d = jd * 16 + tx;
            g_Y[((size_t)b * T_ + q) * C_ + h * HD_ + d] = o[i][jd] * inv;
        }
    }
}

extern "C" void kernel_launch(void* const* d_in, const int* in_sizes, int n_in,
                              void* d_out, int out_size)
{
    const float* x  = (const float*)d_in[0];
    const float* Wq = (const float*)d_in[1];
    const float* bq = (const float*)d_in[2];
    const float* Wk = (const float*)d_in[3];
    const float* bk = (const float*)d_in[4];
    const float* Wv = (const float*)d_in[5];
    const float* bv = (const float*)d_in[6];
    const float* Wp = (const float*)d_in[7];
    const float* bp = (const float*)d_in[8];

    // QKV projections: [4096,1024] @ 3x[1024,1024], scattered to [b,h,t,d]
    qkv_gemm<<<dim3(8, 32, 3), 256>>>(x, Wq, bq, Wk, bk, Wv, bv);

    // Causal flash attention
    const int smem = (64 * 66 + 64 * 67 + 64 * 68) * (int)sizeof(float);  // 51456 B
    cudaFuncSetAttribute(flash_kernel,
                         cudaFuncAttributeMaxDynamicSharedMemorySize, smem);
    flash_kernel<<<dim3(32, 16, 2), 256, smem>>>();

    // Output projection into d_out
    proj_gemm<<<dim3(8, 32), 256>>>(Wp, bp, (float*)d_out);
}

// round 3
// speedup vs baseline: 3.1091x; 3.1091x over previous
#include <cuda_runtime.h>

#define B_  2
#define T_  2048
#define C_  1024
#define H_  16
#define HD_ 64

__device__ float g_Q[(size_t)B_ * H_ * T_ * HD_];
__device__ float g_K[(size_t)B_ * H_ * T_ * HD_];
__device__ float g_V[(size_t)B_ * H_ * T_ * HD_];
__device__ float g_Y[(size_t)B_ * T_ * C_];

// ---------------------------------------------------------------------------
// helpers
// ---------------------------------------------------------------------------
__device__ __forceinline__ unsigned f2tf32(float f) {
    unsigned u; asm("cvt.rna.tf32.f32 %0, %1;" : "=r"(u) : "f"(f)); return u;
}
__device__ __forceinline__ uint4 cvt4_tf32(float4 f) {
    uint4 u; u.x = f2tf32(f.x); u.y = f2tf32(f.y);
    u.z = f2tf32(f.z); u.w = f2tf32(f.w); return u;
}
__device__ __forceinline__ float ex2f(float x) {
    float y; asm("ex2.approx.f32 %0, %1;" : "=f"(y) : "f"(x)); return y;
}
// mma.sync m16n8k8 tf32: D = A@B + D   (family-agnostic; legal on sm_103 base)
__device__ __forceinline__ void mma8(float* c, const unsigned* a, const unsigned* b) {
    asm volatile(
        "mma.sync.aligned.m16n8k8.row.col.f32.tf32.tf32.f32 "
        "{%0,%1,%2,%3}, {%4,%5,%6,%7}, {%8,%9}, {%0,%1,%2,%3};"
        : "+f"(c[0]), "+f"(c[1]), "+f"(c[2]), "+f"(c[3])
        : "r"(a[0]), "r"(a[1]), "r"(a[2]), "r"(a[3]), "r"(b[0]), "r"(b[1]));
}

// ---------------------------------------------------------------------------
// tf32 mma GEMM: Out[4096,1024] = A[4096,1024] @ W[1024,1024] + bias
// CTA 128x128, BK=32, 256 thr (8 warps, warp tile 64x32), double-buffered.
// smem strides: A 36 (A-frag bank 4g+t, conflict-free), B 136 (8t+g, cf).
// ---------------------------------------------------------------------------
#define GEMM_SMEM (17920 * 4)  // 2*128*36 + 2*32*136 floats

__device__ __forceinline__ void tc_gemm(
    const float* __restrict__ A, const float* __restrict__ W,
    const float* __restrict__ bias, float* __restrict__ Out, int scatter)
{
    extern __shared__ float sf[];
    float* As0 = sf;            // 128*36
    float* As1 = sf + 4608;
    float* Bs0 = sf + 9216;     // 32*136
    float* Bs1 = sf + 13568;

    const int tid = threadIdx.x;
    const int lane = tid & 31, wid = tid >> 5;
    const int g = lane >> 2, t = lane & 3;
    const int wm = wid >> 2, wn = wid & 3;
    const int bm0 = blockIdx.y * 128, bn0 = blockIdx.x * 128;

    float acc[4][4][4];
#pragma unroll
    for (int mt = 0; mt < 4; mt++)
#pragma unroll
        for (int nt = 0; nt < 4; nt++)
#pragma unroll
            for (int e = 0; e < 4; e++) acc[mt][nt][e] = 0.f;

    uint4 av[4], bv[4];
#define LD_CHUNK(c)                                                            \
    {                                                                          \
        const int k0 = (c) * 32;                                               \
        _Pragma("unroll")                                                      \
        for (int r = 0; r < 4; r++) {                                          \
            int fi = tid + r * 256;                                            \
            int ar = fi >> 3, ac = (fi & 7) * 4;                               \
            av[r] = cvt4_tf32(*(const float4*)(A + (size_t)(bm0 + ar) * 1024 + k0 + ac)); \
            int br = fi >> 5, bc = (fi & 31) * 4;                              \
            bv[r] = cvt4_tf32(*(const float4*)(W + (size_t)(k0 + br) * 1024 + bn0 + bc)); \
        }                                                                      \
    }
#define ST_CHUNK(Ab, Bb)                                                       \
    {                                                                          \
        _Pragma("unroll")                                                      \
        for (int r = 0; r < 4; r++) {                                          \
            int fi = tid + r * 256;                                            \
            int ar = fi >> 3, ac = (fi & 7) * 4;                               \
            *(uint4*)((Ab) + ar * 36 + ac) = av[r];                            \
            int br = fi >> 5, bc = (fi & 31) * 4;                              \
            *(uint4*)((Bb) + br * 136 + bc) = bv[r];                           \
        }                                                                      \
    }

    LD_CHUNK(0);
    ST_CHUNK(As0, Bs0);
    __syncthreads();

    for (int c = 0; c < 32; c++) {
        const float* Ab = (c & 1) ? As1 : As0;
        const float* Bb = (c & 1) ? Bs1 : Bs0;
        if (c < 31) LD_CHUNK(c + 1);

#pragma unroll
        for (int kk = 0; kk < 4; kk++) {
            unsigned af[4][4], bf[4][2];
#pragma unroll
            for (int mt = 0; mt < 4; mt++) {
                const float* p = Ab + (wm * 64 + mt * 16 + g) * 36 + kk * 8 + t;
                af[mt][0] = __float_as_uint(p[0]);
                af[mt][1] = __float_as_uint(p[8 * 36]);
                af[mt][2] = __float_as_uint(p[4]);
                af[mt][3] = __float_as_uint(p[8 * 36 + 4]);
            }
#pragma unroll
            for (int nt = 0; nt < 4; nt++) {
                const float* p = Bb + (kk * 8 + t) * 136 + wn * 32 + nt * 8 + g;
                bf[nt][0] = __float_as_uint(p[0]);
                bf[nt][1] = __float_as_uint(p[4 * 136]);
            }
#pragma unroll
            for (int mt = 0; mt < 4; mt++)
#pragma unroll
                for (int nt = 0; nt < 4; nt++)
                    mma8(acc[mt][nt], af[mt], bf[nt]);
        }

        if (c < 31) { ST_CHUNK((c & 1) ? As0 : As1, (c & 1) ? Bs0 : Bs1); }
        __syncthreads();
    }

    // epilogue: direct stores (32B-contiguous segments per quad)
#pragma unroll
    for (int mt = 0; mt < 4; mt++) {
#pragma unroll
        for (int nt = 0; nt < 4; nt++) {
            const int col = bn0 + wn * 32 + nt * 8 + 2 * t;
            const float b0 = bias[col], b1 = bias[col + 1];
#pragma unroll
            for (int h = 0; h < 2; h++) {
                const int row = bm0 + wm * 64 + mt * 16 + h * 8 + g;
                float2 v = make_float2(acc[mt][nt][2 * h] + b0,
                                       acc[mt][nt][2 * h + 1] + b1);
                if (scatter) {
                    const int hh = col >> 6, d = col & 63;
                    const int bb = row >> 11, tt = row & 2047;
                    *(float2*)(Out + ((((size_t)bb * H_ + hh) * T_ + tt) << 6) + d) = v;
                } else {
                    *(float2*)(Out + (size_t)row * C_ + col) = v;
                }
            }
        }
    }
}

__global__ void __launch_bounds__(256) qkv_mma(
    const float* __restrict__ X,
    const float* __restrict__ Wq, const float* __restrict__ bq,
    const float* __restrict__ Wk, const float* __restrict__ bk,
    const float* __restrict__ Wv, const float* __restrict__ bv)
{
    const float* W; const float* bb; float* O;
    if (blockIdx.z == 0)      { W = Wq; bb = bq; O = g_Q; }
    else if (blockIdx.z == 1) { W = Wk; bb = bk; O = g_K; }
    else                      { W = Wv; bb = bv; O = g_V; }
    tc_gemm(X, W, bb, O, 1);
}

__global__ void __launch_bounds__(256) proj_mma(
    const float* __restrict__ Wp, const float* __restrict__ bp,
    float* __restrict__ Out)
{
    tc_gemm(g_Y, Wp, bp, Out, 0);
}

// ---------------------------------------------------------------------------
// Flash attention, tf32 mma. CTA = 128 q-rows, 4 warps (warp = 32 rows),
// k-tiles of 64. Softmax warp-local on mma fragments (quad shfl reductions).
// smem: Qs 128x68, Ks 64x68, Vs 64x72, Ps 4x(32x68). 105472 B.
// ---------------------------------------------------------------------------
#define FLASH_SMEM (26368 * 4)
#define CSC 0.18033688011112042f  // 1/sqrt(64) * log2(e)

__global__ void __launch_bounds__(128) flash_mma()
{
    extern __shared__ float sf[];
    float* Qs = sf;             // 128*68
    float* Ks = sf + 8704;      // 64*68
    float* Vs = sf + 13056;     // 64*72
    float* Ps = sf + 17664 + (threadIdx.x >> 5) * 2176;  // per-warp 32*68

    const int tid = threadIdx.x;
    const int lane = tid & 31, w = tid >> 5;
    const int g = lane >> 2, t = lane & 3;

    const int qblk = (int)gridDim.x - 1 - (int)blockIdx.x;  // heavy first
    const int q0 = qblk * 128;
    const int nkt = 2 * qblk + 2;
    const int hh = blockIdx.y, b = blockIdx.z;
    const size_t base = ((size_t)(b * H_ + hh)) * T_ * HD_;
    const float* Qg = g_Q + base;
    const float* Kg = g_K + base;
    const float* Vg = g_V + base;

    // load Q tile (tf32-rounded)
#pragma unroll
    for (int r = 0; r < 16; r++) {
        int fi = tid + r * 128;
        int row = fi >> 4, cq = (fi & 15) * 4;
        *(uint4*)(Qs + row * 68 + cq) =
            cvt4_tf32(*(const float4*)(Qg + (size_t)(q0 + row) * HD_ + cq));
    }

    float oacc[2][8][4];
    float mrow[2][2], lrow[2][2];
#pragma unroll
    for (int mt = 0; mt < 2; mt++) {
        mrow[mt][0] = mrow[mt][1] = -1e30f;
        lrow[mt][0] = lrow[mt][1] = 0.f;
#pragma unroll
        for (int nt = 0; nt < 8; nt++)
#pragma unroll
            for (int e = 0; e < 4; e++) oacc[mt][nt][e] = 0.f;
    }

    for (int kt = 0; kt < nkt; kt++) {
        __syncthreads();  // K/V/Q buffers safe to (re)fill / first-use
#pragma unroll
        for (int r = 0; r < 8; r++) {
            int fi = tid + r * 128;
            int row = fi >> 4, cq = (fi & 15) * 4;
            *(uint4*)(Ks + row * 68 + cq) =
                cvt4_tf32(*(const float4*)(Kg + (size_t)(kt * 64 + row) * HD_ + cq));
            *(uint4*)(Vs + row * 72 + cq) =
                cvt4_tf32(*(const float4*)(Vg + (size_t)(kt * 64 + row) * HD_ + cq));
        }
        __syncthreads();

        // S = Q @ K^T  (warp rows 32w..32w+31)
        float sacc[2][8][4];
#pragma unroll
        for (int mt = 0; mt < 2; mt++)
#pragma unroll
            for (int nt = 0; nt < 8; nt++)
#pragma unroll
                for (int e = 0; e < 4; e++) sacc[mt][nt][e] = 0.f;

#pragma unroll
        for (int kk = 0; kk < 8; kk++) {
            unsigned af[2][4], bf[8][2];
#pragma unroll
            for (int mt = 0; mt < 2; mt++) {
                const float* p = Qs + (32 * w + 16 * mt + g) * 68 + kk * 8 + t;
                af[mt][0] = __float_as_uint(p[0]);
                af[mt][1] = __float_as_uint(p[8 * 68]);
                af[mt][2] = __float_as_uint(p[4]);
                af[mt][3] = __float_as_uint(p[8 * 68 + 4]);
            }
#pragma unroll
            for (int nt = 0; nt < 8; nt++) {
                const float* p = Ks + (nt * 8 + g) * 68 + kk * 8 + t;
                bf[nt][0] = __float_as_uint(p[0]);
                bf[nt][1] = __float_as_uint(p[4]);
            }
#pragma unroll
            for (int mt = 0; mt < 2; mt++)
#pragma unroll
                for (int nt = 0; nt < 8; nt++)
                    mma8(sacc[mt][nt], af[mt], bf[nt]);
        }

        // scale (+ causal mask on last two tiles)
        if (kt >= nkt - 2) {
#pragma unroll
            for (int mt = 0; mt < 2; mt++)
#pragma unroll
                for (int nt = 0; nt < 8; nt++)
#pragma unroll
                    for (int e = 0; e < 4; e++) {
                        const int col = kt * 64 + nt * 8 + 2 * t + (e & 1);
                        const int row = q0 + 32 * w + 16 * mt + 8 * (e >> 1) + g;
                        float v = sacc[mt][nt][e] * CSC;
                        sacc[mt][nt][e] = (col > row) ? -1e30f : v;
                    }
        } else {
#pragma unroll
            for (int mt = 0; mt < 2; mt++)
#pragma unroll
                for (int nt = 0; nt < 8; nt++)
#pragma unroll
                    for (int e = 0; e < 4; e++) sacc[mt][nt][e] *= CSC;
        }

        // online softmax (base-2), P tf32-rounded before l-sum and PV
#pragma unroll
        for (int mt = 0; mt < 2; mt++) {
#pragma unroll
            for (int h = 0; h < 2; h++) {
                float mx = -1e30f;
#pragma unroll
                for (int nt = 0; nt < 8; nt++)
                    mx = fmaxf(mx, fmaxf(sacc[mt][nt][2 * h], sacc[mt][nt][2 * h + 1]));
                mx = fmaxf(mx, __shfl_xor_sync(0xffffffffu, mx, 1));
                mx = fmaxf(mx, __shfl_xor_sync(0xffffffffu, mx, 2));
                const float mo = mrow[mt][h];
                const float mn = fmaxf(mo, mx);
                const float alpha = ex2f(mo - mn);
                mrow[mt][h] = mn;
                float rs = 0.f;
#pragma unroll
                for (int nt = 0; nt < 8; nt++) {
                    float p0 = __uint_as_float(f2tf32(ex2f(sacc[mt][nt][2 * h] - mn)));
                    float p1 = __uint_as_float(f2tf32(ex2f(sacc[mt][nt][2 * h + 1] - mn)));
                    rs += p0 + p1;
                    *(float2*)(Ps + (16 * mt + 8 * h + g) * 68 + nt * 8 + 2 * t) =
                        make_float2(p0, p1);
                    oacc[mt][nt][2 * h]     *= alpha;
                    oacc[mt][nt][2 * h + 1] *= alpha;
                }
                rs += __shfl_xor_sync(0xffffffffu, rs, 1);
                rs += __shfl_xor_sync(0xffffffffu, rs, 2);
                lrow[mt][h] = lrow[mt][h] * alpha + rs;
            }
        }
        __syncwarp();

        // O += P @ V
#pragma unroll
        for (int kk = 0; kk < 8; kk++) {
            unsigned af[2][4], bf[8][2];
#pragma unroll
            for (int mt = 0; mt < 2; mt++) {
                const float* p = Ps + (16 * mt + g) * 68 + kk * 8 + t;
                af[mt][0] = __float_as_uint(p[0]);
                af[mt][1] = __float_as_uint(p[8 * 68]);
                af[mt][2] = __float_as_uint(p[4]);
                af[mt][3] = __float_as_uint(p[8 * 68 + 4]);
            }
#pragma unroll
            for (int nt = 0; nt < 8; nt++) {
                const float* p = Vs + (kk * 8 + t) * 72 + nt * 8 + g;
                bf[nt][0] = __float_as_uint(p[0]);
                bf[nt][1] = __float_as_uint(p[4 * 72]);
            }
#pragma unroll
            for (int mt = 0; mt < 2; mt++)
#pragma unroll
                for (int nt = 0; nt < 8; nt++)
                    mma8(oacc[mt][nt], af[mt], bf[nt]);
        }
        __syncwarp();  // PV reads of Ps done before next-iter softmax overwrites
    }

    // normalize + write [b,t,c]
#pragma unroll
    for (int mt = 0; mt < 2; mt++)
#pragma unroll
        for (int h = 0; h < 2; h++) {
            const float inv = 1.0f / lrow[mt][h];
            const int row = q0 + 32 * w + 16 * mt + 8 * h + g;
#pragma unroll
            for (int nt = 0; nt < 8; nt++) {
                const int d = nt * 8 + 2 * t;
                *(float2*)(g_Y + ((size_t)b * T_ + row) * C_ + hh * HD_ + d) =
                    make_float2(oacc[mt][nt][2 * h] * inv,
                                oacc[mt][nt][2 * h + 1] * inv);
            }
        }
}

extern "C" void kernel_launch(void* const* d_in, const int* in_sizes, int n_in,
                              void* d_out, int out_size)
{
    const float* x  = (const float*)d_in[0];
    const float* Wq = (const float*)d_in[1];
    const float* bq = (const float*)d_in[2];
    const float* Wk = (const float*)d_in[3];
    const float* bk = (const float*)d_in[4];
    const float* Wv = (const float*)d_in[5];
    const float* bv = (const float*)d_in[6];
    const float* Wp = (const float*)d_in[7];
    const float* bp = (const float*)d_in[8];

    cudaFuncSetAttribute(qkv_mma,  cudaFuncAttributeMaxDynamicSharedMemorySize, GEMM_SMEM);
    cudaFuncSetAttribute(proj_mma, cudaFuncAttributeMaxDynamicSharedMemorySize, GEMM_SMEM);
    cudaFuncSetAttribute(flash_mma, cudaFuncAttributeMaxDynamicSharedMemorySize, FLASH_SMEM);

    qkv_mma<<<dim3(8, 32, 3), 256, GEMM_SMEM>>>(x, Wq, bq, Wk, bk, Wv, bv);
    flash_mma<<<dim3(16, 16, 2), 128, FLASH_SMEM>>>();
    proj_mma<<<dim3(8, 32), 256, GEMM_SMEM>>>(Wp, bp, (float*)d_out);
}